// round 9
// baseline (speedup 1.0000x reference)
#include <cuda_runtime.h>

// loss = 0.5 * ( sum_j ( (y-mu)^2/sigma + log(sigma) ) + NT*log(2*pi) ) / (NT*BS)
// over the LAST row only (reference selects log_prob[-1]).
//
// R6: R5 math (minimal MUFU: 8 RCP + 2 LG2 per thread via pairwise folding,
// pair products reused by the log term) + split-barrier reduction tail:
// warps 1-3 bar.arrive (non-blocking), warp 0 bar.sync then gathers 4 partials.
//
// sigma in [0.1,1.1] => pair prods in [0.01,1.21], prod8 in [1e-8,2.2]: fp32-safe.

#define BS 4096
#define NT 2048
#define THREADS 128          // 128 threads * 16 floats = 2048 = NT

__global__ void __launch_bounds__(THREADS, 1)
criterion_last_row_kernel(const float* __restrict__ mu,
                          const float* __restrict__ sigma,
                          const float* __restrict__ ty,
                          float* __restrict__ out) {
    const long long base = (long long)(BS - 1) * NT;
    const int tid = threadIdx.x;

    const float4* m4p = reinterpret_cast<const float4*>(mu + base);
    const float4* s4p = reinterpret_cast<const float4*>(sigma + base);
    const float4* y4p = reinterpret_cast<const float4*>(ty + base);

    // 4 float4 groups per array; all 12 loads independent (front-batched MLP).
    float4 m[4], s[4], y[4];
    #pragma unroll
    for (int g = 0; g < 4; g++) {
        m[g] = m4p[tid + g * THREADS];
        s[g] = s4p[tid + g * THREADS];
        y[g] = y4p[tid + g * THREADS];
    }

    float acc = 0.0f;
    float p4[4];
    #pragma unroll
    for (int g = 0; g < 4; g++) {
        const float dx = y[g].x - m[g].x;
        const float dy = y[g].y - m[g].y;
        const float dz = y[g].z - m[g].z;
        const float dw = y[g].w - m[g].w;
        const float pxy = s[g].x * s[g].y;      // reused for log term
        const float pzw = s[g].z * s[g].w;      // reused for log term
        const float nxy = dx * dx * s[g].y + dy * dy * s[g].x;
        const float nzw = dz * dz * s[g].w + dw * dw * s[g].z;
        acc += __fdividef(nxy, pxy);
        acc += __fdividef(nzw, pzw);
        p4[g] = pxy * pzw;
    }
    // log terms: one __logf per 8-element product (2 per thread)
    acc += __logf(p4[0] * p4[1]) + __logf(p4[2] * p4[3]);

    // warp reduce (butterfly)
    #pragma unroll
    for (int off = 16; off > 0; off >>= 1)
        acc += __shfl_xor_sync(0xFFFFFFFFu, acc, off);

    __shared__ float warp_sums[THREADS / 32];
    const int wid = tid >> 5;
    const int lid = tid & 31;
    if (lid == 0) warp_sums[wid] = acc;

    if (wid != 0) {
        // producers: non-blocking arrive, then done
        asm volatile("bar.arrive 0, %0;" :: "r"(THREADS) : "memory");
    } else {
        // consumer warp: sync drains the STS from all warps
        asm volatile("bar.sync 0, %0;" :: "r"(THREADS) : "memory");
        float v = (lid < THREADS / 32) ? warp_sums[lid] : 0.0f;
        v += __shfl_xor_sync(0xFFFFFFFFu, v, 2);
        v += __shfl_xor_sync(0xFFFFFFFFu, v, 1);
        if (lid == 0) {
            const float LOG_2PI = 1.8378770664093453f;
            const float INV_SCALE = 0.5f / ((float)NT * (float)BS);
            out[0] = (v + (float)NT * LOG_2PI) * INV_SCALE;
        }
    }
}

extern "C" void kernel_launch(void* const* d_in, const int* in_sizes, int n_in,
                              void* d_out, int out_size) {
    const float* mu    = (const float*)d_in[0];
    const float* sigma = (const float*)d_in[1];
    const float* ty    = (const float*)d_in[2];
    float* out = (float*)d_out;
    criterion_last_row_kernel<<<1, THREADS>>>(mu, sigma, ty, out);
}

// round 11
// speedup vs baseline: 1.4085x; 1.4085x over previous
#include <cuda_runtime.h>

// loss = 0.5 * ( sum_j ( (y-mu)^2/sigma + log(sigma) ) + NT*log(2*pi) ) / (NT*BS)
// over the LAST row only (reference selects log_prob[-1]).
//
// R10: R5 math (pairwise division folding: 8 MUFU.RCP + 2 MUFU.LG2 per thread,
// pair products reused by the log term), 4 warps (one per SMSP), 12
// front-batched LDG.128 per thread. Tail: per-warp SHFL butterfly -> STS,
// __syncthreads, then lane 0 of warp 0 reads all 4 partials with ONE LDS.128
// and sums locally (removes 2 dependent SHFLs, ~40 cyc off the chain).
//
// sigma in [0.1,1.1] => pair prods in [0.01,1.21], prod8 in [1e-8,2.2]: fp32-safe.

#define BS 4096
#define NT 2048
#define THREADS 128          // 128 threads * 16 floats = 2048 = NT

__global__ void __launch_bounds__(THREADS, 1)
criterion_last_row_kernel(const float* __restrict__ mu,
                          const float* __restrict__ sigma,
                          const float* __restrict__ ty,
                          float* __restrict__ out) {
    const long long base = (long long)(BS - 1) * NT;
    const int tid = threadIdx.x;

    const float4* m4p = reinterpret_cast<const float4*>(mu + base);
    const float4* s4p = reinterpret_cast<const float4*>(sigma + base);
    const float4* y4p = reinterpret_cast<const float4*>(ty + base);

    // 4 float4 groups per array; all 12 loads independent (front-batched MLP).
    float4 m[4], s[4], y[4];
    #pragma unroll
    for (int g = 0; g < 4; g++) {
        m[g] = m4p[tid + g * THREADS];
        s[g] = s4p[tid + g * THREADS];
        y[g] = y4p[tid + g * THREADS];
    }

    float acc = 0.0f;
    float p4[4];
    #pragma unroll
    for (int g = 0; g < 4; g++) {
        const float dx = y[g].x - m[g].x;
        const float dy = y[g].y - m[g].y;
        const float dz = y[g].z - m[g].z;
        const float dw = y[g].w - m[g].w;
        const float pxy = s[g].x * s[g].y;      // reused for log term
        const float pzw = s[g].z * s[g].w;      // reused for log term
        const float nxy = dx * dx * s[g].y + dy * dy * s[g].x;
        const float nzw = dz * dz * s[g].w + dw * dw * s[g].z;
        acc += __fdividef(nxy, pxy);
        acc += __fdividef(nzw, pzw);
        p4[g] = pxy * pzw;
    }
    // log terms: one __logf per 8-element product (2 per thread)
    acc += __logf(p4[0] * p4[1]) + __logf(p4[2] * p4[3]);

    // per-warp reduce (SHFL butterfly)
    #pragma unroll
    for (int off = 16; off > 0; off >>= 1)
        acc += __shfl_xor_sync(0xFFFFFFFFu, acc, off);

    __shared__ __align__(16) float warp_sums[THREADS / 32];  // 4 floats, 16B
    const int wid = tid >> 5;
    const int lid = tid & 31;
    if (lid == 0) warp_sums[wid] = acc;
    __syncthreads();

    if (tid == 0) {
        // single LDS.128 gathers all 4 warp partials; local serial sum
        const float4 ws = *reinterpret_cast<const float4*>(warp_sums);
        const float v = (ws.x + ws.y) + (ws.z + ws.w);
        const float LOG_2PI = 1.8378770664093453f;
        const float INV_SCALE = 0.5f / ((float)NT * (float)BS);
        out[0] = (v + (float)NT * LOG_2PI) * INV_SCALE;
    }
}

extern "C" void kernel_launch(void* const* d_in, const int* in_sizes, int n_in,
                              void* d_out, int out_size) {
    const float* mu    = (const float*)d_in[0];
    const float* sigma = (const float*)d_in[1];
    const float* ty    = (const float*)d_in[2];
    float* out = (float*)d_out;
    criterion_last_row_kernel<<<1, THREADS>>>(mu, sigma, ty, out);
}